// round 16
// baseline (speedup 1.0000x reference)
#include <cuda_runtime.h>

#define BB 8
#define CC 256
#define HH 96
#define WW 96
#define HS 192
#define WS 192
#define OC 32
#define GG 4
#define CG 64   // CC/GG

typedef unsigned long long u64;

// Offset field scratch: [B][G][HS][WS] x float2 (x-offset, y-offset) interleaved
__device__ float g_off[BB * GG * HS * WS * 2];

#define FMA_F32X2(d, a, b) \
    asm("fma.rn.f32x2 %0, %1, %2, %0;" : "+l"(d) : "l"(a), "l"(b))
#define PACK_F32X2(out, lo, hi) \
    asm("mov.b64 %0, {%1, %2};" : "=l"(out) : "f"(lo), "f"(hi))
#define UNPACK_F32X2(lo, hi, in) \
    asm("mov.b64 {%0, %1}, %2;" : "=f"(lo), "=f"(hi) : "l"(in))

// ---------------------------------------------------------------------------
// Kernel 1: 1x1 conv + tanh + pixel_shuffle(2).
// Warp-split: warps 0-3 compute outputs 0..15, warps 4-7 outputs 16..31,
// for the same 128 pixel-PAIRS per block. Each warp does 4 uniform
// LDS.128 per channel (halved smem traffic vs 8); the x LDG.64 (2 adjacent
// pixels) is duplicated across halves but dedups in L1.
// ---------------------------------------------------------------------------
__global__ __launch_bounds__(256) void conv_offset_kernel(
    const float* __restrict__ x, const float* __restrict__ w,
    const float* __restrict__ bias)
{
    __shared__ __align__(16) float wT[CC * OC];  // wT[c*32 + o]
    int tid = threadIdx.x;
    #pragma unroll
    for (int k = 0; k < (CC * OC) / 256; ++k) {
        int flat = tid + k * 256;
        int c = flat >> 5, o = flat & 31;
        wT[flat] = w[o * CC + c];
    }
    __syncthreads();

    int half = tid >> 7;                    // 0: outputs 0-15, 1: outputs 16-31
    int q    = tid & 127;                   // pair slot within block
    int pr   = blockIdx.x * 128 + q;        // pair index 0 .. 36863
    int b    = pr / (HH * WW / 2);
    int rem  = pr - b * (HH * WW / 2);
    int h    = rem / (WW / 2);
    int wp0  = (rem - h * (WW / 2)) * 2;    // even column of the pair

    // 16 outputs per pixel as 8 f32x2 accumulators; two pixels
    u64 acc0[8], acc1[8];
    #pragma unroll
    for (int m = 0; m < 8; ++m) {
        PACK_F32X2(acc0[m], __ldg(bias + half * 16 + 2 * m),
                            __ldg(bias + half * 16 + 2 * m + 1));
        acc1[m] = acc0[m];
    }

    const float* xp = x + (b * CC) * (HH * WW) + h * WW + wp0;
    const float* wh = wT + half * 16;

    #pragma unroll 1
    for (int c0 = 0; c0 < CC; c0 += 8) {
        float2 xv[8];
        #pragma unroll
        for (int u = 0; u < 8; ++u)                 // 8 independent LDG.64
            xv[u] = __ldg((const float2*)(xp + (c0 + u) * (HH * WW)));
        #pragma unroll
        for (int u = 0; u < 8; ++u) {
            u64 xx0, xx1;
            PACK_F32X2(xx0, xv[u].x, xv[u].x);
            PACK_F32X2(xx1, xv[u].y, xv[u].y);
            const ulonglong2* wrow =
                (const ulonglong2*)(wh + (c0 + u) * OC);
            #pragma unroll
            for (int t = 0; t < 4; ++t) {           // 4 uniform LDS.128
                ulonglong2 wv = wrow[t];
                FMA_F32X2(acc0[2 * t + 0], xx0, wv.x);
                FMA_F32X2(acc0[2 * t + 1], xx0, wv.y);
                FMA_F32X2(acc1[2 * t + 0], xx1, wv.x);
                FMA_F32X2(acc1[2 * t + 1], xx1, wv.y);
            }
        }
    }

    // pixel_shuffle(2) + tanh + scatter into interleaved (x,y) offset field
    #pragma unroll
    for (int px = 0; px < 2; ++px) {
        const u64* acc = px ? acc1 : acc0;
        int wp = wp0 + px;
        #pragma unroll
        for (int m = 0; m < 8; ++m) {
            float a0, a1;
            UNPACK_F32X2(a0, a1, acc[m]);
            #pragma unroll
            for (int s = 0; s < 2; ++s) {
                int o    = half * 16 + 2 * m + s;
                float v  = tanhf(s ? a1 : a0);
                int co   = o >> 2;          // 0..7  channel after shuffle
                int i    = (o >> 1) & 1;    // row sub-position
                int j    = o & 1;           // col sub-position
                int gidx = co >> 1;         // group 0..3
                int k    = co & 1;          // 0 = x-offset, 1 = y-offset
                int hs = 2 * h + i, ws = 2 * wp + j;
                g_off[((((b * GG + gidx) * HS + hs) * WS + ws) << 1) + k] = v;
            }
        }
    }
}

// ---------------------------------------------------------------------------
// Kernel 2: smem-staged bilinear grid_sample.
// Block = (b, g, 8-row output band). Source rows [h0-7, h0+10] (<=18 rows,
// 6.9KB/ch) staged per channel into double-buffered smem with coalesced
// LDG.128; gathers become scattered LDS.32 (bank-spread by lane<->column).
// Warp = output row; lane l handles ws pairs {2l, 2l+64, 2l+128}.
// ---------------------------------------------------------------------------
__global__ __launch_bounds__(256, 3) void gather_kernel(
    const float* __restrict__ x, float* __restrict__ out)
{
    __shared__ __align__(16) float sbuf[2][18 * WW];

    int tid  = threadIdx.x;
    int bg   = blockIdx.x / 24;             // 0..31 = b*4 + g
    int band = blockIdx.x - bg * 24;        // 0..23
    int b    = bg >> 2;
    int g    = bg & 3;
    int hs0  = band * 8;                    // output rows hs0..hs0+7
    int h0   = band * 4;
    int y_lo = max(0, h0 - 7);
    int y_hi = min(HH - 1, h0 + 10);
    int R    = y_hi - y_lo + 1;             // 11..18 staged rows

    int lane = tid & 31, wrp = tid >> 5;    // warp = output row
    int hs   = hs0 + wrp;

    // precompute 6 sample points (3 pairs)
    int   a00[6], adx[6], ady[6];
    float w00[6], w01[6], w10[6], w11[6];
    #pragma unroll
    for (int jp = 0; jp < 3; ++jp) {
        int ws0 = 2 * lane + 64 * jp;
        float4 oo = __ldg((const float4*)g_off
                          + (((bg * HS + hs) * WS + ws0) >> 1));
        float ox[2] = {oo.x, oo.z};
        float oy[2] = {oo.y, oo.w};
        #pragma unroll
        for (int j = 0; j < 2; ++j) {
            int e = jp * 2 + j;
            float gx = (float)(ws0 + j) * 0.5f - 0.25f + 6.0f * ox[j];
            float gy = (float)hs        * 0.5f - 0.25f + 6.0f * oy[j];
            gx = fminf(fmaxf(gx, 0.0f), (float)(WW - 1));
            gy = fminf(fmaxf(gy, 0.0f), (float)(HH - 1));
            int x0 = (int)gx;
            int y0 = (int)gy;
            float wx = gx - (float)x0;
            float wy = gy - (float)y0;
            a00[e] = (y0 - y_lo) * WW + x0;
            adx[e] = (x0 < WW - 1) ? 1  : 0;
            ady[e] = (y0 < HH - 1) ? WW : 0;
            w00[e] = (1.0f - wx) * (1.0f - wy);
            w01[e] = wx * (1.0f - wy);
            w10[e] = (1.0f - wx) * wy;
            w11[e] = wx * wy;
        }
    }

    const float* xplane = x + (b * CC + g * CG) * (HH * WW) + y_lo * WW;
    float*       op     = out + ((b * CC + g * CG) * HS + hs) * WS;

    int nload = R * (WW / 4);               // float4 count (<=432)

    // stage channel 0
    {
        const float4* src = (const float4*)xplane;
        float4* dst = (float4*)sbuf[0];
        for (int i = tid; i < nload; i += 256)
            dst[i] = __ldg(src + i);
    }

    #pragma unroll 1
    for (int c = 0; c < CG; ++c) {
        __syncthreads();                    // staged buf[c&1] ready
        if (c + 1 < CG) {                   // prefetch next channel
            const float4* src =
                (const float4*)(xplane + (c + 1) * (HH * WW));
            float4* dst = (float4*)sbuf[(c + 1) & 1];
            for (int i = tid; i < nload; i += 256)
                dst[i] = __ldg(src + i);
        }
        const float* s = sbuf[c & 1];
        #pragma unroll
        for (int jp = 0; jp < 3; ++jp) {
            float2 r;
            {
                int e = jp * 2;
                int i00 = a00[e], i10 = i00 + ady[e];
                float v00 = s[i00], v01 = s[i00 + adx[e]];
                float v10 = s[i10], v11 = s[i10 + adx[e]];
                r.x = v00 * w00[e] + v01 * w01[e] + v10 * w10[e] + v11 * w11[e];
            }
            {
                int e = jp * 2 + 1;
                int i00 = a00[e], i10 = i00 + ady[e];
                float v00 = s[i00], v01 = s[i00 + adx[e]];
                float v10 = s[i10], v11 = s[i10 + adx[e]];
                r.y = v00 * w00[e] + v01 * w01[e] + v10 * w10[e] + v11 * w11[e];
            }
            __stcs((float2*)(op + 2 * lane + 64 * jp), r);
        }
        op += HS * WS;
    }
}

extern "C" void kernel_launch(void* const* d_in, const int* in_sizes, int n_in,
                              void* d_out, int out_size) {
    const float* x    = (const float*)d_in[0];
    const float* w    = (const float*)d_in[1];
    const float* bias = (const float*)d_in[2];
    float* out        = (float*)d_out;

    conv_offset_kernel<<<(BB * HH * WW / 2) / 128, 256>>>(x, w, bias);
    gather_kernel<<<BB * GG * 24, 256>>>(x, out);
}

// round 17
// speedup vs baseline: 1.1608x; 1.1608x over previous
#include <cuda_runtime.h>

#define BB 8
#define CC 256
#define HH 96
#define WW 96
#define HS 192
#define WS 192
#define OC 32
#define GG 4
#define CG 64   // CC/GG

typedef unsigned long long u64;

// Offset field scratch: [B][G][HS][WS] x float2 (x-offset, y-offset) interleaved
__device__ float g_off[BB * GG * HS * WS * 2];

#define FMA_F32X2(d, a, b) \
    asm("fma.rn.f32x2 %0, %1, %2, %0;" : "+l"(d) : "l"(a), "l"(b))
#define ADD_F32X2(d, a, b) \
    asm("add.rn.f32x2 %0, %1, %2;" : "=l"(d) : "l"(a), "l"(b))
#define PACK_F32X2(out, lo, hi) \
    asm("mov.b64 %0, {%1, %2};" : "=l"(out) : "f"(lo), "f"(hi))
#define UNPACK_F32X2(lo, hi, in) \
    asm("mov.b64 {%0, %1}, %2;" : "=f"(lo), "=f"(hi) : "l"(in))

// ---------------------------------------------------------------------------
// Kernel 1: 1x1 conv + tanh + pixel_shuffle(2).
// LANE-PAIR CHANNEL SPLIT: lanes 2k/2k+1 share one pixel; lane parity picks
// channels [0,128) vs [128,256). Doubles resident warps (latency hiding) at
// unchanged chip-wide LDG/LDS/FFMA totals. Reduction = 16 shfl.xor(1) +
// packed f32x2 adds; even lane does tanh + scatter.
// ---------------------------------------------------------------------------
__global__ __launch_bounds__(256) void conv_offset_kernel(
    const float* __restrict__ x, const float* __restrict__ w,
    const float* __restrict__ bias)
{
    __shared__ __align__(16) float wT[CC * OC];  // wT[c*32 + o]
    int tid = threadIdx.x;
    #pragma unroll
    for (int k = 0; k < (CC * OC) / 256; ++k) {
        int flat = tid + k * 256;
        int c = flat >> 5, o = flat & 31;
        wT[flat] = w[o * CC + c];
    }
    __syncthreads();

    int half = tid & 1;                     // channel half
    int pl   = tid >> 1;                    // local pixel 0..127
    int p    = blockIdx.x * 128 + pl;       // 0 .. B*H*W-1
    int b    = p / (HH * WW);
    int rem  = p - b * (HH * WW);
    int h    = rem / WW;
    int wp   = rem - h * WW;

    u64 acc[OC / 2];
    #pragma unroll
    for (int q = 0; q < OC / 2; ++q) acc[q] = 0ull;

    const float* xp    = x + (b * CC + half * 128) * (HH * WW) + h * WW + wp;
    const float* wbase = wT + half * 128 * OC;

    float xa[8], xb[8];
    #pragma unroll
    for (int u = 0; u < 8; ++u)
        xa[u] = __ldg(xp + u * (HH * WW));

    #pragma unroll 1
    for (int c0 = 0; c0 < 128; c0 += 8) {
        if (c0 + 8 < 128) {
            #pragma unroll
            for (int u = 0; u < 8; ++u)             // prefetch next batch
                xb[u] = __ldg(xp + (c0 + 8 + u) * (HH * WW));
        }
        #pragma unroll
        for (int u = 0; u < 8; ++u) {
            u64 xx;
            PACK_F32X2(xx, xa[u], xa[u]);
            const ulonglong2* wrow =
                (const ulonglong2*)(wbase + (c0 + u) * OC);
            #pragma unroll
            for (int q = 0; q < OC / 4; ++q) {
                ulonglong2 wv = wrow[q];            // LDS.128 (2-way bcast)
                FMA_F32X2(acc[2 * q + 0], xx, wv.x);
                FMA_F32X2(acc[2 * q + 1], xx, wv.y);
            }
        }
        #pragma unroll
        for (int u = 0; u < 8; ++u) xa[u] = xb[u];
    }

    // cross-half reduction: partner lane differs only in channel half
    #pragma unroll
    for (int q = 0; q < OC / 2; ++q) {
        u64 other = __shfl_xor_sync(0xffffffffu, acc[q], 1);
        ADD_F32X2(acc[q], acc[q], other);
    }
    if (half) return;

    // pixel_shuffle(2) + tanh + scatter into interleaved (x,y) offset field
    #pragma unroll
    for (int q = 0; q < OC / 2; ++q) {
        float a0, a1;
        UNPACK_F32X2(a0, a1, acc[q]);
        a0 += __ldg(bias + 2 * q);
        a1 += __ldg(bias + 2 * q + 1);
        #pragma unroll
        for (int s = 0; s < 2; ++s) {
            int o    = 2 * q + s;
            float v  = tanhf(s ? a1 : a0);
            int co   = o >> 2;          // 0..7  channel after shuffle
            int i    = (o >> 1) & 1;    // row sub-position
            int j    = o & 1;           // col sub-position
            int gidx = co >> 1;         // group 0..3
            int k    = co & 1;          // 0 = x-offset, 1 = y-offset
            int hs = 2 * h + i, ws = 2 * wp + j;
            g_off[((((b * GG + gidx) * HS + hs) * WS + ws) << 1) + k] = v;
        }
    }
}

// ---------------------------------------------------------------------------
// Kernel 2: bilinear border grid_sample. One thread = 2 horizontally adjacent
// output pixels -> STG.64 streaming stores, one LDG.128 for both offset
// pairs, 8 independent gather LDGs per channel iteration, unroll 4.
// (unchanged from the 81.2us best)
// ---------------------------------------------------------------------------
__global__ __launch_bounds__(256) void gather_kernel(
    const float* __restrict__ x, float* __restrict__ out)
{
    const int tiles = (HS * WS / 2) / 256;  // 72 pair-tiles per (b,g)
    int bg   = blockIdx.x / tiles;          // 0..31 = b*4 + gidx
    int t    = (blockIdx.x - bg * tiles) * 256 + threadIdx.x;
    int hs   = t / (WS / 2);
    int ws0  = (t - hs * (WS / 2)) * 2;     // even column of the pair
    int b    = bg >> 2;
    int gidx = bg & 3;

    // both offset pairs in one LDG.128: (x0,y0,x1,y1)
    float4 oo = __ldg((const float4*)g_off + (((bg * HS + hs) * WS + ws0) >> 1));
    float offx[2] = {oo.x, oo.z};
    float offy[2] = {oo.y, oo.w};

    int   i00[2], dx[2], dy[2];
    float w00[2], w01[2], w10[2], w11[2];
    #pragma unroll
    for (int j = 0; j < 2; ++j) {
        // grid math collapsed: gx = (base_x + 0.125*off + 1)*48 - 0.5
        float gx = (float)(ws0 + j) * 0.5f - 0.25f + 6.0f * offx[j];
        float gy = (float)hs        * 0.5f - 0.25f + 6.0f * offy[j];
        gx = fminf(fmaxf(gx, 0.0f), (float)(WW - 1));
        gy = fminf(fmaxf(gy, 0.0f), (float)(HH - 1));
        int x0 = (int)gx;   // floor (gx >= 0)
        int y0 = (int)gy;
        float wx = gx - (float)x0;
        float wy = gy - (float)y0;
        dx[j]  = (x0 < WW - 1) ? 1  : 0;
        dy[j]  = (y0 < HH - 1) ? WW : 0;
        i00[j] = y0 * WW + x0;
        w00[j] = (1.0f - wx) * (1.0f - wy);
        w01[j] = wx * (1.0f - wy);
        w10[j] = (1.0f - wx) * wy;
        w11[j] = wx * wy;
    }

    const float* xp = x + (b * CC + gidx * CG) * (HH * WW);
    float*       op = out + ((b * CC + gidx * CG) * HS + hs) * WS + ws0;

    #pragma unroll 4
    for (int c = 0; c < CG; ++c) {
        float v[8];
        #pragma unroll
        for (int j = 0; j < 2; ++j) {               // 8 independent LDGs
            v[4 * j + 0] = __ldg(xp + i00[j]);
            v[4 * j + 1] = __ldg(xp + i00[j] + dx[j]);
            v[4 * j + 2] = __ldg(xp + i00[j] + dy[j]);
            v[4 * j + 3] = __ldg(xp + i00[j] + dy[j] + dx[j]);
        }
        float2 r;
        r.x = v[0] * w00[0] + v[1] * w01[0] + v[2] * w10[0] + v[3] * w11[0];
        r.y = v[4] * w00[1] + v[5] * w01[1] + v[6] * w10[1] + v[7] * w11[1];
        __stcs((float2*)op, r);                     // streaming store
        xp += HH * WW;
        op += HS * WS;
    }
}

extern "C" void kernel_launch(void* const* d_in, const int* in_sizes, int n_in,
                              void* d_out, int out_size) {
    const float* x    = (const float*)d_in[0];
    const float* w    = (const float*)d_in[1];
    const float* bias = (const float*)d_in[2];
    float* out        = (float*)d_out;

    conv_offset_kernel<<<(BB * HH * WW) / 128, 256>>>(x, w, bias);
    gather_kernel<<<BB * GG * ((HS * WS / 2) / 256), 256>>>(x, out);
}